// round 1
// baseline (speedup 1.0000x reference)
#include <cuda_runtime.h>

#define BB 256
#define NN 400
#define DD 256
#define DEGC 32
#define EE (BB*NN*DEGC)        // 3276800
#define KK 200
#define NCC (NN-KK)            // 200
#define NT (BB*NN)             // 102400
#define BK (BB*KK)             // 51200
#define BC (BB*NCC)            // 51200

// output offsets (float32 elements)
#define OFF_DIS   ((size_t)0)
#define OFF_COM   ((size_t)BK*DD)                 // 13107200
#define OFF_PERM  (OFF_COM + (size_t)BC*DD)       // 26214400
#define OFF_PERMC (OFF_PERM + BK)                 // 26265600
#define OFF_SOFT  (OFF_PERMC + BC)                // 26316800
#define OFF_EDIS  (OFF_SOFT + NT)                 // 26419200
#define OFF_ECOM  (OFF_EDIS + EE)                 // 29696000

__device__ float g_h[NT];
__device__ float g_agg[NT];
__device__ float g_score[NT];
__device__ int   g_deg_out[NT];
__device__ int   g_deg_in[NT];
__device__ unsigned char g_sel[NT];
__device__ int   g_perm[BK];
__device__ int   g_permc[BC];
__device__ unsigned int g_maxbits;
__device__ float g_sumexp;

__device__ __forceinline__ unsigned enc_f(float f) {
    unsigned u = __float_as_uint(f);
    return (u >> 31) ? ~u : (u | 0x80000000u);
}
__device__ __forceinline__ float dec_f(unsigned u) {
    return __uint_as_float((u >> 31) ? (u & 0x7FFFFFFFu) : ~u);
}

__global__ void k_zero() {
    int i = blockIdx.x * blockDim.x + threadIdx.x;
    if (i < NT) { g_agg[i] = 0.f; g_deg_out[i] = 0; g_deg_in[i] = 0; }
    if (i == 0) { g_maxbits = 0u; g_sumexp = 0.f; }
}

__global__ void k_deg(const int* __restrict__ src, const int* __restrict__ dst) {
    int i = blockIdx.x * blockDim.x + threadIdx.x;
    if (i >= EE / 4) return;
    int4 s = ((const int4*)src)[i];
    int4 d = ((const int4*)dst)[i];
    atomicAdd(&g_deg_out[s.x], 1); atomicAdd(&g_deg_out[s.y], 1);
    atomicAdd(&g_deg_out[s.z], 1); atomicAdd(&g_deg_out[s.w], 1);
    atomicAdd(&g_deg_in[d.x], 1);  atomicAdd(&g_deg_in[d.y], 1);
    atomicAdd(&g_deg_in[d.z], 1);  atomicAdd(&g_deg_in[d.w], 1);
}

// warp-per-node dot(feature_row, W) * deg_out^-1/2
__global__ void __launch_bounds__(256) k_xw(const float* __restrict__ feat,
                                            const float* __restrict__ W) {
    __shared__ __align__(16) float sW[DD];
    int t = threadIdx.x;
    for (int i = t; i < DD; i += blockDim.x) sW[i] = W[i];
    __syncthreads();
    int warp = t >> 5, lane = t & 31;
    int node = blockIdx.x * (blockDim.x >> 5) + warp;
    if (node >= NT) return;
    const float4* f4 = (const float4*)(feat + (size_t)node * DD);
    const float4* w4 = (const float4*)sW;
    float acc = 0.f;
#pragma unroll
    for (int j = 0; j < 2; j++) {
        float4 v = f4[lane * 2 + j];
        float4 w = w4[lane * 2 + j];
        acc += v.x * w.x + v.y * w.y + v.z * w.z + v.w * w.w;
    }
#pragma unroll
    for (int o = 16; o > 0; o >>= 1) acc += __shfl_down_sync(0xffffffffu, acc, o);
    if (lane == 0) {
        float nrm = rsqrtf(fmaxf((float)g_deg_out[node], 1.f));
        g_h[node] = acc * nrm;
    }
}

__global__ void k_agg(const int* __restrict__ src, const int* __restrict__ dst) {
    int i = blockIdx.x * blockDim.x + threadIdx.x;
    if (i >= EE / 4) return;
    int4 s = ((const int4*)src)[i];
    int4 d = ((const int4*)dst)[i];
    atomicAdd(&g_agg[d.x], g_h[s.x]);
    atomicAdd(&g_agg[d.y], g_h[s.y]);
    atomicAdd(&g_agg[d.z], g_h[s.z]);
    atomicAdd(&g_agg[d.w], g_h[s.w]);
}

__global__ void __launch_bounds__(256) k_score(const float* __restrict__ b) {
    __shared__ float sm[256];
    int i = blockIdx.x * blockDim.x + threadIdx.x;
    float v = -3.4e38f;
    if (i < NT) {
        float s = g_agg[i] * rsqrtf(fmaxf((float)g_deg_in[i], 1.f)) + b[0];
        g_score[i] = s;
        v = s;
    }
    sm[threadIdx.x] = v;
    __syncthreads();
    for (int o = 128; o > 0; o >>= 1) {
        if (threadIdx.x < o) sm[threadIdx.x] = fmaxf(sm[threadIdx.x], sm[threadIdx.x + o]);
        __syncthreads();
    }
    if (threadIdx.x == 0) atomicMax(&g_maxbits, enc_f(sm[0]));
}

__global__ void __launch_bounds__(256) k_sumexp() {
    __shared__ float sm[256];
    float m = dec_f(g_maxbits);
    int i = blockIdx.x * blockDim.x + threadIdx.x;
    float v = (i < NT) ? expf(g_score[i] - m) : 0.f;
    sm[threadIdx.x] = v;
    __syncthreads();
    for (int o = 128; o > 0; o >>= 1) {
        if (threadIdx.x < o) sm[threadIdx.x] += sm[threadIdx.x + o];
        __syncthreads();
    }
    if (threadIdx.x == 0) atomicAdd(&g_sumexp, sm[0]);
}

// one block per graph: bitonic sort 512 keys (score desc, idx asc), top-K + complement
__global__ void __launch_bounds__(256) k_topk(float* __restrict__ out) {
    __shared__ unsigned long long keys[512];
    __shared__ int scan[512];
    __shared__ unsigned char flags[512];
    int g = blockIdx.x;
    int t = threadIdx.x;
    const float* sc = g_score + (size_t)g * NN;
    for (int i = t; i < 512; i += 256) {
        unsigned long long key;
        if (i < NN) {
            unsigned u = enc_f(sc[i]);
            key = (((unsigned long long)(~u)) << 32) | (unsigned)i;
        } else {
            key = 0xFFFFFFFFFFFFFFFFull;
        }
        keys[i] = key;
        flags[i] = 0;
    }
    __syncthreads();
    for (int k = 2; k <= 512; k <<= 1) {
        for (int j = k >> 1; j > 0; j >>= 1) {
            for (int i = t; i < 512; i += 256) {
                int ixj = i ^ j;
                if (ixj > i) {
                    bool up = ((i & k) == 0);
                    unsigned long long a = keys[i], c = keys[ixj];
                    if ((a > c) == up) { keys[i] = c; keys[ixj] = a; }
                }
            }
            __syncthreads();
        }
    }
    // selected ranks 0..K-1 (ascending key = descending score)
    for (int r = t; r < KK; r += 256) {
        int local = (int)(keys[r] & 0xffffffffu);
        flags[local] = 1;
        int gid = g * NN + local;
        g_perm[g * KK + r] = gid;
        out[OFF_PERM + (size_t)g * KK + r] = (float)gid;
    }
    __syncthreads();
    for (int i = t; i < 512; i += 256) {
        if (i < NN) g_sel[(size_t)g * NN + i] = flags[i];
        scan[i] = (i < NN && !flags[i]) ? 1 : 0;
    }
    __syncthreads();
    // inclusive Hillis-Steele scan over 512
    for (int off = 1; off < 512; off <<= 1) {
        int i1 = t + 256;
        int v0 = scan[t]  + ((t  >= off) ? scan[t  - off] : 0);
        int v1 = scan[i1] + ((i1 >= off) ? scan[i1 - off] : 0);
        __syncthreads();
        scan[t] = v0; scan[i1] = v1;
        __syncthreads();
    }
    for (int i = t; i < NN; i += 256) {
        if (!flags[i]) {
            int p = scan[i] - 1;          // ascending local id among unselected
            int gid = g * NN + i;
            g_permc[g * NCC + p] = gid;
            out[OFF_PERMC + (size_t)g * NCC + p] = (float)gid;
        }
    }
}

// fused gated gather: rows [0,BK) -> dis, rows [BK,NT) -> com
__global__ void __launch_bounds__(256) k_gather(const float* __restrict__ feat,
                                                float* __restrict__ out) {
    int t = threadIdx.x;
    int rowInBlk = t >> 6;        // 4 rows per block, 64 threads (float4) per row
    int lane = t & 63;
    long row = (long)blockIdx.x * 4 + rowInBlk;
    if (row >= NT) return;
    int node; size_t obase;
    if (row < BK) {
        node = g_perm[row];
        obase = OFF_DIS + (size_t)row * DD;
    } else {
        long r2 = row - BK;
        node = g_permc[r2];
        obase = OFF_COM + (size_t)r2 * DD;
    }
    float gate = tanhf(g_score[node]);
    const float4* f4 = (const float4*)(feat + (size_t)node * DD);
    float4 v = f4[lane];
    v.x *= gate; v.y *= gate; v.z *= gate; v.w *= gate;
    ((float4*)(out + obase))[lane] = v;
}

__global__ void k_soft(float* __restrict__ out) {
    int i = blockIdx.x * blockDim.x + threadIdx.x;
    if (i >= NT) return;
    float m = dec_f(g_maxbits);
    out[OFF_SOFT + i] = expf(g_score[i] - m) / g_sumexp;
}

__global__ void k_mask(const int* __restrict__ src, const int* __restrict__ dst,
                       float* __restrict__ out) {
    int i = blockIdx.x * blockDim.x + threadIdx.x;
    if (i >= EE / 4) return;
    int4 s = ((const int4*)src)[i];
    int4 d = ((const int4*)dst)[i];
    unsigned char sx = g_sel[s.x], sy = g_sel[s.y], sz = g_sel[s.z], sw = g_sel[s.w];
    unsigned char dx = g_sel[d.x], dy = g_sel[d.y], dz = g_sel[d.z], dw = g_sel[d.w];
    float4 dis, com;
    dis.x = (sx & dx) ? 1.f : 0.f;  com.x = (!sx & !dx) ? 1.f : 0.f;
    dis.y = (sy & dy) ? 1.f : 0.f;  com.y = (!sy & !dy) ? 1.f : 0.f;
    dis.z = (sz & dz) ? 1.f : 0.f;  com.z = (!sz & !dz) ? 1.f : 0.f;
    dis.w = (sw & dw) ? 1.f : 0.f;  com.w = (!sw & !dw) ? 1.f : 0.f;
    ((float4*)(out + OFF_EDIS))[i] = dis;
    ((float4*)(out + OFF_ECOM))[i] = com;
}

extern "C" void kernel_launch(void* const* d_in, const int* in_sizes, int n_in,
                              void* d_out, int out_size) {
    const float* feat = (const float*)d_in[0];
    const float* W    = (const float*)d_in[1];
    const float* b    = (const float*)d_in[2];
    const int*   src  = (const int*)d_in[3];
    const int*   dst  = (const int*)d_in[4];
    float* out = (float*)d_out;
    (void)in_sizes; (void)n_in; (void)out_size;

    k_zero<<<(NT + 255) / 256, 256>>>();
    k_deg<<<(EE / 4 + 255) / 256, 256>>>(src, dst);
    k_xw<<<NT / 8, 256>>>(feat, W);
    k_agg<<<(EE / 4 + 255) / 256, 256>>>(src, dst);
    k_score<<<NT / 256, 256>>>(b);
    k_sumexp<<<NT / 256, 256>>>();
    k_topk<<<BB, 256>>>(out);
    k_gather<<<NT / 4, 256>>>(feat, out);
    k_soft<<<NT / 256, 256>>>(out);
    k_mask<<<EE / 4 / 256, 256>>>(src, dst, out);
}

// round 2
// speedup vs baseline: 1.2616x; 1.2616x over previous
#include <cuda_runtime.h>

#define BB 256
#define NN 400
#define DD 256
#define DEGC 32
#define EE (BB*NN*DEGC)        // 3276800
#define KK 200
#define NCC (NN-KK)            // 200
#define NT (BB*NN)             // 102400
#define BK (BB*KK)             // 51200
#define BC (BB*NCC)            // 51200
#define EG (NN*DEGC)           // 12800 edges per graph
#define EG4 (EG/4)             // 3200

// output offsets (float32 elements)
#define OFF_DIS   ((size_t)0)
#define OFF_COM   ((size_t)BK*DD)                 // 13107200
#define OFF_PERM  (OFF_COM + (size_t)BC*DD)       // 26214400
#define OFF_PERMC (OFF_PERM + BK)                 // 26265600
#define OFF_SOFT  (OFF_PERMC + BC)                // 26316800
#define OFF_EDIS  (OFF_SOFT + NT)                 // 26419200
#define OFF_ECOM  (OFF_EDIS + EE)                 // 29696000

__device__ float2 g_nodeacc[NT];   // x = deg_in (float count), y = agg
__device__ int    g_deg_out[NT];
__device__ float  g_p[NT];         // raw feature @ W (no norm)
__device__ float  g_score[NT];
__device__ int    g_perm[BK];
__device__ int    g_permc[BC];
__device__ unsigned int g_maxbits;
__device__ float  g_sumexp;

__device__ __forceinline__ unsigned enc_f(float f) {
    unsigned u = __float_as_uint(f);
    return (u >> 31) ? ~u : (u | 0x80000000u);
}
__device__ __forceinline__ float dec_f(unsigned u) {
    return __uint_as_float((u >> 31) ? (u & 0x7FFFFFFFu) : ~u);
}

__global__ void k_init() {
    int i = blockIdx.x * blockDim.x + threadIdx.x;
    if (i < NT) { g_nodeacc[i] = make_float2(0.f, 0.f); g_deg_out[i] = 0; }
    if (i == 0) { g_maxbits = 0u; g_sumexp = 0.f; }
}

// Heterogeneous grid: 4-of-5 blocks do p = feat@W (warp per node),
// 1-of-5 blocks do deg_out atomics. Independent workloads overlap on chip.
// grid = 16000 blocks of 256 threads.
__global__ void __launch_bounds__(256) k_xw_deg(const float* __restrict__ feat,
                                                const float* __restrict__ W,
                                                const int* __restrict__ src) {
    int b = blockIdx.x;
    if ((b % 5) == 4) {
        // degree part: chunk b/5 in [0,3200)
        int i = (b / 5) * 256 + threadIdx.x;   // [0, EE/4)
        int4 s = ((const int4*)src)[i];
        atomicAdd(&g_deg_out[s.x], 1); atomicAdd(&g_deg_out[s.y], 1);
        atomicAdd(&g_deg_out[s.z], 1); atomicAdd(&g_deg_out[s.w], 1);
        return;
    }
    __shared__ __align__(16) float sW[DD];
    int t = threadIdx.x;
    for (int i = t; i < DD; i += 256) sW[i] = W[i];
    __syncthreads();
    int chunk = (b / 5) * 4 + (b % 5);         // [0, 12800)
    int warp = t >> 5, lane = t & 31;
    int node = chunk * 8 + warp;
    const float4* f4 = (const float4*)(feat + (size_t)node * DD);
    const float4* w4 = (const float4*)sW;
    float acc = 0.f;
#pragma unroll
    for (int j = 0; j < 2; j++) {
        float4 v = f4[lane * 2 + j];
        float4 w = w4[lane * 2 + j];
        acc += v.x * w.x + v.y * w.y + v.z * w.z + v.w * w.w;
    }
#pragma unroll
    for (int o = 16; o > 0; o >>= 1) acc += __shfl_down_sync(0xffffffffu, acc, o);
    if (lane == 0) g_p[node] = acc;
}

// Fused deg_in + agg via one float2 atomic per edge.
__global__ void __launch_bounds__(256) k_agg(const int* __restrict__ src,
                                             const int* __restrict__ dst) {
    int i = blockIdx.x * blockDim.x + threadIdx.x;
    if (i >= EE / 4) return;
    int4 s = ((const int4*)src)[i];
    int4 d = ((const int4*)dst)[i];
    float h0 = g_p[s.x] * rsqrtf(fmaxf((float)g_deg_out[s.x], 1.f));
    float h1 = g_p[s.y] * rsqrtf(fmaxf((float)g_deg_out[s.y], 1.f));
    float h2 = g_p[s.z] * rsqrtf(fmaxf((float)g_deg_out[s.z], 1.f));
    float h3 = g_p[s.w] * rsqrtf(fmaxf((float)g_deg_out[s.w], 1.f));
    atomicAdd(&g_nodeacc[d.x], make_float2(1.f, h0));
    atomicAdd(&g_nodeacc[d.y], make_float2(1.f, h1));
    atomicAdd(&g_nodeacc[d.z], make_float2(1.f, h2));
    atomicAdd(&g_nodeacc[d.w], make_float2(1.f, h3));
}

// One block per graph: score + global-max contribution + bitonic topk +
// perm/permc writes + edge-mask writes (this graph's contiguous edge range).
__global__ void __launch_bounds__(256) k_topk(const float* __restrict__ bptr,
                                              const int* __restrict__ src,
                                              const int* __restrict__ dst,
                                              float* __restrict__ out) {
    __shared__ unsigned long long keys[512];
    __shared__ int scan[512];
    __shared__ unsigned char flags[512];
    __shared__ float ssc[NN];
    __shared__ float smax[256];
    int g = blockIdx.x;
    int t = threadIdx.x;
    float b0 = bptr[0];

    // scores for this graph's 400 nodes
    float lmax = -3.4e38f;
    for (int i = t; i < NN; i += 256) {
        float2 a = g_nodeacc[(size_t)g * NN + i];
        float s = a.y * rsqrtf(fmaxf(a.x, 1.f)) + b0;
        ssc[i] = s;
        g_score[(size_t)g * NN + i] = s;
        lmax = fmaxf(lmax, s);
    }
    smax[t] = lmax;
    __syncthreads();
    for (int o = 128; o > 0; o >>= 1) {
        if (t < o) smax[t] = fmaxf(smax[t], smax[t + o]);
        __syncthreads();
    }
    if (t == 0) atomicMax(&g_maxbits, enc_f(smax[0]));

    // keys: (score desc, idx asc)
    for (int i = t; i < 512; i += 256) {
        unsigned long long key;
        if (i < NN) {
            unsigned u = enc_f(ssc[i]);
            key = (((unsigned long long)(~u)) << 32) | (unsigned)i;
        } else {
            key = 0xFFFFFFFFFFFFFFFFull;
        }
        keys[i] = key;
        flags[i] = 0;
    }
    __syncthreads();
    for (int k = 2; k <= 512; k <<= 1) {
        for (int j = k >> 1; j > 0; j >>= 1) {
            for (int i = t; i < 512; i += 256) {
                int ixj = i ^ j;
                if (ixj > i) {
                    bool up = ((i & k) == 0);
                    unsigned long long a = keys[i], c = keys[ixj];
                    if ((a > c) == up) { keys[i] = c; keys[ixj] = a; }
                }
            }
            __syncthreads();
        }
    }
    for (int r = t; r < KK; r += 256) {
        int local = (int)(keys[r] & 0xffffffffu);
        flags[local] = 1;
        int gid = g * NN + local;
        g_perm[g * KK + r] = gid;
        out[OFF_PERM + (size_t)g * KK + r] = (float)gid;
    }
    __syncthreads();
    for (int i = t; i < 512; i += 256)
        scan[i] = (i < NN && !flags[i]) ? 1 : 0;
    __syncthreads();
    // inclusive Hillis-Steele scan over 512
    for (int off = 1; off < 512; off <<= 1) {
        int i1 = t + 256;
        int v0 = scan[t]  + ((t  >= off) ? scan[t  - off] : 0);
        int v1 = scan[i1] + ((i1 >= off) ? scan[i1 - off] : 0);
        __syncthreads();
        scan[t] = v0; scan[i1] = v1;
        __syncthreads();
    }
    for (int i = t; i < NN; i += 256) {
        if (!flags[i]) {
            int p = scan[i] - 1;
            int gid = g * NN + i;
            g_permc[g * NCC + p] = gid;
            out[OFF_PERMC + (size_t)g * NCC + p] = (float)gid;
        }
    }
    __syncthreads();

    // edge masks for this graph's contiguous edge range
    const int4* s4 = (const int4*)src + (size_t)g * EG4;
    const int4* d4 = (const int4*)dst + (size_t)g * EG4;
    float4* odis = (float4*)(out + OFF_EDIS) + (size_t)g * EG4;
    float4* ocom = (float4*)(out + OFF_ECOM) + (size_t)g * EG4;
    int base = g * NN;
    for (int i = t; i < EG4; i += 256) {
        int4 s = s4[i];
        int4 d = d4[i];
        unsigned char sx = flags[s.x - base], sy = flags[s.y - base];
        unsigned char sz = flags[s.z - base], sw = flags[s.w - base];
        unsigned char dx = flags[d.x - base], dy = flags[d.y - base];
        unsigned char dz = flags[d.z - base], dw = flags[d.w - base];
        float4 dis, com;
        dis.x = (sx & dx) ? 1.f : 0.f;  com.x = (!sx && !dx) ? 1.f : 0.f;
        dis.y = (sy & dy) ? 1.f : 0.f;  com.y = (!sy && !dy) ? 1.f : 0.f;
        dis.z = (sz & dz) ? 1.f : 0.f;  com.z = (!sz && !dz) ? 1.f : 0.f;
        dis.w = (sw & dw) ? 1.f : 0.f;  com.w = (!sw && !dw) ? 1.f : 0.f;
        odis[i] = dis;
        ocom[i] = com;
    }
}

__global__ void __launch_bounds__(256) k_sumexp() {
    __shared__ float sm[256];
    float m = dec_f(g_maxbits);
    int i = blockIdx.x * blockDim.x + threadIdx.x;
    float v = (i < NT) ? expf(g_score[i] - m) : 0.f;
    sm[threadIdx.x] = v;
    __syncthreads();
    for (int o = 128; o > 0; o >>= 1) {
        if (threadIdx.x < o) sm[threadIdx.x] += sm[threadIdx.x + o];
        __syncthreads();
    }
    if (threadIdx.x == 0) atomicAdd(&g_sumexp, sm[0]);
}

// fused gated gather + softmax write: rows [0,BK) -> dis, [BK,NT) -> com.
// Every node appears exactly once, so lane 0 also writes its softmax entry.
__global__ void __launch_bounds__(256) k_gather(const float* __restrict__ feat,
                                                float* __restrict__ out) {
    int t = threadIdx.x;
    int rowInBlk = t >> 6;        // 4 rows per block, 64 threads (float4) per row
    int lane = t & 63;
    long row = (long)blockIdx.x * 4 + rowInBlk;
    int node; size_t obase;
    if (row < BK) {
        node = g_perm[row];
        obase = OFF_DIS + (size_t)row * DD;
    } else {
        long r2 = row - BK;
        node = g_permc[r2];
        obase = OFF_COM + (size_t)r2 * DD;
    }
    float sc = g_score[node];
    float gate = tanhf(sc);
    const float4* f4 = (const float4*)(feat + (size_t)node * DD);
    float4 v = f4[lane];
    v.x *= gate; v.y *= gate; v.z *= gate; v.w *= gate;
    ((float4*)(out + obase))[lane] = v;
    if (lane == 0) {
        float m = dec_f(g_maxbits);
        out[OFF_SOFT + node] = expf(sc - m) / g_sumexp;
    }
}

extern "C" void kernel_launch(void* const* d_in, const int* in_sizes, int n_in,
                              void* d_out, int out_size) {
    const float* feat = (const float*)d_in[0];
    const float* W    = (const float*)d_in[1];
    const float* b    = (const float*)d_in[2];
    const int*   src  = (const int*)d_in[3];
    const int*   dst  = (const int*)d_in[4];
    float* out = (float*)d_out;
    (void)in_sizes; (void)n_in; (void)out_size;

    k_init<<<(NT + 255) / 256, 256>>>();
    k_xw_deg<<<16000, 256>>>(feat, W, src);
    k_agg<<<(EE / 4 + 255) / 256, 256>>>(src, dst);
    k_topk<<<BB, 256>>>(b, src, dst, out);
    k_sumexp<<<NT / 256, 256>>>();
    k_gather<<<NT / 4, 256>>>(feat, out);
}

// round 4
// speedup vs baseline: 1.2829x; 1.0169x over previous
#include <cuda_runtime.h>

#define BB 256
#define NN 400
#define DD 256
#define DEGC 32
#define EE (BB*NN*DEGC)        // 3276800
#define KK 200
#define NCC (NN-KK)            // 200
#define NT (BB*NN)             // 102400
#define BK (BB*KK)             // 51200
#define BC (BB*NCC)            // 51200
#define EG (NN*DEGC)           // 12800 edges per graph
#define EG4 (EG/4)             // 3200

// output offsets (float32 elements)
#define OFF_DIS   ((size_t)0)
#define OFF_COM   ((size_t)BK*DD)                 // 13107200
#define OFF_PERM  (OFF_COM + (size_t)BC*DD)       // 26214400
#define OFF_PERMC (OFF_PERM + BK)                 // 26265600
#define OFF_SOFT  (OFF_PERMC + BC)                // 26316800
#define OFF_EDIS  (OFF_SOFT + NT)                 // 26419200
#define OFF_ECOM  (OFF_EDIS + EE)                 // 29696000

// Deterministic packed accumulator per node:
//   bits [56:64) : deg_in count
//   bits [0:56)  : sum over edges of (fixed + 2^47), fixed = llrint(h * 2^28)
// Integer atomics are order-invariant -> bitwise identical scores every run.
#define AGG_SCALE 268435456.0           // 2^28
#define AGG_BIAS  (1ll << 47)
#define MASK56    ((1ull << 56) - 1ull)

__device__ unsigned long long g_acc[NT];
__device__ int    g_deg_out[NT];
__device__ float  g_p[NT];         // raw feature @ W (no norm)
__device__ float  g_score[NT];
__device__ int    g_perm[BK];
__device__ int    g_permc[BC];
__device__ float  g_sumexp;

__device__ __forceinline__ unsigned enc_f(float f) {
    unsigned u = __float_as_uint(f);
    return (u >> 31) ? ~u : (u | 0x80000000u);
}

__global__ void k_init() {
    int i = blockIdx.x * blockDim.x + threadIdx.x;
    if (i < NT) { g_acc[i] = 0ull; g_deg_out[i] = 0; }
    if (i == 0) g_sumexp = 0.f;
}

// Heterogeneous grid: 4-of-5 blocks do p = feat@W (warp per node),
// 1-of-5 blocks do deg_out atomics. Independent workloads overlap on chip.
// grid = 16000 blocks of 256 threads.
__global__ void __launch_bounds__(256) k_xw_deg(const float* __restrict__ feat,
                                                const float* __restrict__ W,
                                                const int* __restrict__ src) {
    int b = blockIdx.x;
    if ((b % 5) == 4) {
        int i = (b / 5) * 256 + threadIdx.x;   // [0, EE/4)
        int4 s = ((const int4*)src)[i];
        atomicAdd(&g_deg_out[s.x], 1); atomicAdd(&g_deg_out[s.y], 1);
        atomicAdd(&g_deg_out[s.z], 1); atomicAdd(&g_deg_out[s.w], 1);
        return;
    }
    __shared__ __align__(16) float sW[DD];
    int t = threadIdx.x;
    for (int i = t; i < DD; i += 256) sW[i] = W[i];
    __syncthreads();
    int chunk = (b / 5) * 4 + (b % 5);         // [0, 12800)
    int warp = t >> 5, lane = t & 31;
    int node = chunk * 8 + warp;
    const float4* f4 = (const float4*)(feat + (size_t)node * DD);
    const float4* w4 = (const float4*)sW;
    float acc = 0.f;
#pragma unroll
    for (int j = 0; j < 2; j++) {
        float4 v = f4[lane * 2 + j];
        float4 w = w4[lane * 2 + j];
        acc += v.x * w.x + v.y * w.y + v.z * w.z + v.w * w.w;
    }
#pragma unroll
    for (int o = 16; o > 0; o >>= 1) acc += __shfl_down_sync(0xffffffffu, acc, o);
    if (lane == 0) g_p[node] = acc;
}

__device__ __forceinline__ unsigned long long pack_edge(float h) {
    long long fixedv = llrint((double)h * AGG_SCALE);
    return (1ull << 56) + (unsigned long long)(fixedv + AGG_BIAS);
}

// Fused deg_in + agg via one deterministic u64 atomic per edge.
__global__ void __launch_bounds__(256) k_agg(const int* __restrict__ src,
                                             const int* __restrict__ dst) {
    int i = blockIdx.x * blockDim.x + threadIdx.x;
    if (i >= EE / 4) return;
    int4 s = ((const int4*)src)[i];
    int4 d = ((const int4*)dst)[i];
    float h0 = g_p[s.x] * rsqrtf(fmaxf((float)g_deg_out[s.x], 1.f));
    float h1 = g_p[s.y] * rsqrtf(fmaxf((float)g_deg_out[s.y], 1.f));
    float h2 = g_p[s.z] * rsqrtf(fmaxf((float)g_deg_out[s.z], 1.f));
    float h3 = g_p[s.w] * rsqrtf(fmaxf((float)g_deg_out[s.w], 1.f));
    atomicAdd(&g_acc[d.x], pack_edge(h0));
    atomicAdd(&g_acc[d.y], pack_edge(h1));
    atomicAdd(&g_acc[d.z], pack_edge(h2));
    atomicAdd(&g_acc[d.w], pack_edge(h3));
}

// One block (512 threads) per graph: score + sum-exp + bitonic topk +
// perm/permc writes + edge-mask writes (this graph's contiguous edge range).
__global__ void __launch_bounds__(512) k_topk(const float* __restrict__ bptr,
                                              const int* __restrict__ src,
                                              const int* __restrict__ dst,
                                              float* __restrict__ out) {
    __shared__ unsigned long long keys[512];
    __shared__ int scan[512];
    __shared__ unsigned char flags[512];
    __shared__ float ssc[NN];
    __shared__ float sred[512];
    int g = blockIdx.x;
    int t = threadIdx.x;
    float b0 = bptr[0];

    // decode scores + local exp-sum for this graph's 400 nodes
    float lsum = 0.f;
    if (t < NN) {
        unsigned long long v = g_acc[(size_t)g * NN + t];
        unsigned C = (unsigned)(v >> 56);
        long long S = (long long)(v & MASK56);
        double agg = (double)(S - ((long long)C << 47)) * (1.0 / AGG_SCALE);
        float s = (float)agg * rsqrtf(fmaxf((float)C, 1.f)) + b0;
        ssc[t] = s;
        g_score[(size_t)g * NN + t] = s;
        lsum = expf(s);
    }
    sred[t] = lsum;
    __syncthreads();
    for (int o = 256; o > 0; o >>= 1) {
        if (t < o) sred[t] += sred[t + o];
        __syncthreads();
    }
    if (t == 0) atomicAdd(&g_sumexp, sred[0]);

    // keys: (score desc, idx asc) — one key per thread
    {
        unsigned long long key;
        if (t < NN) {
            unsigned u = enc_f(ssc[t]);
            key = (((unsigned long long)(~u)) << 32) | (unsigned)t;
        } else {
            key = 0xFFFFFFFFFFFFFFFFull;
        }
        keys[t] = key;
        flags[t] = 0;
    }
    __syncthreads();
    for (int k = 2; k <= 512; k <<= 1) {
        for (int j = k >> 1; j > 0; j >>= 1) {
            int ixj = t ^ j;
            if (ixj > t) {
                bool up = ((t & k) == 0);
                unsigned long long a = keys[t], c = keys[ixj];
                if ((a > c) == up) { keys[t] = c; keys[ixj] = a; }
            }
            __syncthreads();
        }
    }
    if (t < KK) {
        int local = (int)(keys[t] & 0xffffffffu);
        flags[local] = 1;
        int gid = g * NN + local;
        g_perm[g * KK + t] = gid;
        out[OFF_PERM + (size_t)g * KK + t] = (float)gid;
    }
    __syncthreads();
    scan[t] = (t < NN && !flags[t]) ? 1 : 0;
    __syncthreads();
    // inclusive Hillis-Steele scan over 512 (one element per thread)
    for (int off = 1; off < 512; off <<= 1) {
        int add = (t >= off) ? scan[t - off] : 0;
        __syncthreads();
        scan[t] += add;
        __syncthreads();
    }
    if (t < NN && !flags[t]) {
        int p = scan[t] - 1;
        int gid = g * NN + t;
        g_permc[g * NCC + p] = gid;
        out[OFF_PERMC + (size_t)g * NCC + p] = (float)gid;
    }
    __syncthreads();

    // edge masks for this graph's contiguous edge range
    const int4* s4 = (const int4*)src + (size_t)g * EG4;
    const int4* d4 = (const int4*)dst + (size_t)g * EG4;
    float4* odis = (float4*)(out + OFF_EDIS) + (size_t)g * EG4;
    float4* ocom = (float4*)(out + OFF_ECOM) + (size_t)g * EG4;
    int base = g * NN;
    for (int i = t; i < EG4; i += 512) {
        int4 s = s4[i];
        int4 d = d4[i];
        unsigned char sx = flags[s.x - base], sy = flags[s.y - base];
        unsigned char sz = flags[s.z - base], sw = flags[s.w - base];
        unsigned char dx = flags[d.x - base], dy = flags[d.y - base];
        unsigned char dz = flags[d.z - base], dw = flags[d.w - base];
        float4 dis, com;
        dis.x = (sx & dx) ? 1.f : 0.f;  com.x = (!sx && !dx) ? 1.f : 0.f;
        dis.y = (sy & dy) ? 1.f : 0.f;  com.y = (!sy && !dy) ? 1.f : 0.f;
        dis.z = (sz & dz) ? 1.f : 0.f;  com.z = (!sz && !dz) ? 1.f : 0.f;
        dis.w = (sw & dw) ? 1.f : 0.f;  com.w = (!sw && !dw) ? 1.f : 0.f;
        odis[i] = dis;
        ocom[i] = com;
    }
}

// fused gated gather + softmax write: rows [0,BK) -> dis, [BK,NT) -> com.
// Every node appears exactly once, so lane 0 also writes its softmax entry.
__global__ void __launch_bounds__(256) k_gather(const float* __restrict__ feat,
                                                float* __restrict__ out) {
    int t = threadIdx.x;
    int rowInBlk = t >> 6;        // 4 rows per block, 64 threads (float4) per row
    int lane = t & 63;
    long row = (long)blockIdx.x * 4 + rowInBlk;
    int node; size_t obase;
    if (row < BK) {
        node = g_perm[row];
        obase = OFF_DIS + (size_t)row * DD;
    } else {
        long r2 = row - BK;
        node = g_permc[r2];
        obase = OFF_COM + (size_t)r2 * DD;
    }
    float sc = g_score[node];
    float gate = tanhf(sc);
    const float4* f4 = (const float4*)(feat + (size_t)node * DD);
    float4 v = f4[lane];
    v.x *= gate; v.y *= gate; v.z *= gate; v.w *= gate;
    ((float4*)(out + obase))[lane] = v;
    if (lane == 0) out[OFF_SOFT + node] = expf(sc) / g_sumexp;
}

extern "C" void kernel_launch(void* const* d_in, const int* in_sizes, int n_in,
                              void* d_out, int out_size) {
    const float* feat = (const float*)d_in[0];
    const float* W    = (const float*)d_in[1];
    const float* b    = (const float*)d_in[2];
    const int*   src  = (const int*)d_in[3];
    const int*   dst  = (const int*)d_in[4];
    float* out = (float*)d_out;
    (void)in_sizes; (void)n_in; (void)out_size;

    k_init<<<(NT + 255) / 256, 256>>>();
    k_xw_deg<<<16000, 256>>>(feat, W, src);
    k_agg<<<(EE / 4 + 255) / 256, 256>>>(src, dst);
    k_topk<<<BB, 512>>>(b, src, dst, out);
    k_gather<<<NT / 4, 256>>>(feat, out);
}